// round 6
// baseline (speedup 1.0000x reference)
#include <cuda_runtime.h>

// Per-frame precomputed matrices: M[f] = initial_extrinsics[f] @ inv(c2w[f])
// 10000 frames x 4 float4 rows = 640 KB static device scratch.
#define NF_MAX 10000
__device__ float4 g_M[NF_MAX * 4];

// ---------------------------------------------------------------------------
// Phase 1: per-frame precompute, all fp32 (~2us).
// ---------------------------------------------------------------------------
__global__ void precompute_kernel(const float* __restrict__ r,
                                  const float* __restrict__ t,
                                  const float* __restrict__ E,
                                  int nf) {
    int f = blockIdx.x * blockDim.x + threadIdx.x;
    if (f >= nf) return;

    float v0 = r[3 * f + 0];
    float v1 = r[3 * f + 1];
    float v2 = r[3 * f + 2];

    float n = sqrtf(v0 * v0 + v1 * v1 + v2 * v2) + 1e-15f;
    float sn, cn;
    __sincosf(n, &sn, &cn);
    float a = sn / n;
    float b = (1.0f - cn) / (n * n);

    // Reference vec2skew (transpose of standard skew):
    float S[3][3] = {{0.0f,  v2, -v1},
                     {-v2, 0.0f,  v0},
                     { v1, -v0, 0.0f}};

    float S2[3][3];
#pragma unroll
    for (int i = 0; i < 3; i++)
#pragma unroll
        for (int j = 0; j < 3; j++)
            S2[i][j] = S[i][0] * S[0][j] + S[i][1] * S[1][j] + S[i][2] * S[2][j];

    float R[3][3];
#pragma unroll
    for (int i = 0; i < 3; i++)
#pragma unroll
        for (int j = 0; j < 3; j++)
            R[i][j] = (i == j ? 1.0f : 0.0f) + a * S[i][j] + b * S2[i][j];

    // rigid inverse of c2w
    float tv0 = t[3 * f + 0];
    float tv1 = t[3 * f + 1];
    float tv2 = t[3 * f + 2];

    float Inv[3][4];
#pragma unroll
    for (int i = 0; i < 3; i++) {
        Inv[i][0] = R[0][i];
        Inv[i][1] = R[1][i];
        Inv[i][2] = R[2][i];
        Inv[i][3] = -(R[0][i] * tv0 + R[1][i] * tv1 + R[2][i] * tv2);
    }

    const float4* E0 = (const float4*)(E + 16 * f);
#pragma unroll
    for (int i = 0; i < 4; i++) {
        float4 e = E0[i];
        float4 row;
        row.x = e.x * Inv[0][0] + e.y * Inv[1][0] + e.z * Inv[2][0];
        row.y = e.x * Inv[0][1] + e.y * Inv[1][1] + e.z * Inv[2][1];
        row.z = e.x * Inv[0][2] + e.y * Inv[1][2] + e.z * Inv[2][2];
        row.w = e.x * Inv[0][3] + e.y * Inv[1][3] + e.z * Inv[2][3] + e.w;
        g_M[f * 4 + i] = row;
    }
}

// ---------------------------------------------------------------------------
// Phase 2: gather. Quad-lane layout (4 lanes of a ray fetch its 64B entry in
// one warp LDG -> 1 L1 wavefront/ray). Table reads via __ldcg: the 640KB
// table cannot live in 228KB L1 anyway — skip L1 fills, serve from L2, and
// keep L1 free for stores. ILP=8 for request batching within LSU cap.
// ---------------------------------------------------------------------------
#define GATHER_ILP 8
__global__ void __launch_bounds__(256) gather_kernel(
        const int* __restrict__ cam,
        float4* __restrict__ out,
        int n_chunks, int nf) {
    int base = blockIdx.x * (blockDim.x * GATHER_ILP) + threadIdx.x;

    if (base + (GATHER_ILP - 1) * blockDim.x < n_chunks) {
        float4 v[GATHER_ILP];
#pragma unroll
        for (int k = 0; k < GATHER_ILP; k++) {
            int c = base + k * blockDim.x;
            int ray = c >> 2;
            int q   = c & 3;
            int f = __ldg(&cam[ray]);
            f = min(max(f, 0), nf - 1);
            v[k] = __ldcg(&g_M[f * 4 + q]);   // L2-only: no L1 fill churn
        }
#pragma unroll
        for (int k = 0; k < GATHER_ILP; k++)
            out[base + k * blockDim.x] = v[k];
    } else {
#pragma unroll
        for (int k = 0; k < GATHER_ILP; k++) {
            int c = base + k * blockDim.x;
            if (c < n_chunks) {
                int ray = c >> 2;
                int q   = c & 3;
                int f = __ldg(&cam[ray]);
                f = min(max(f, 0), nf - 1);
                out[c] = __ldcg(&g_M[f * 4 + q]);
            }
        }
    }
}

extern "C" void kernel_launch(void* const* d_in, const int* in_sizes, int n_in,
                              void* d_out, int out_size) {
    const float* r   = (const float*)d_in[0];   // (NF, 3)
    const float* t   = (const float*)d_in[1];   // (NF, 3)
    const float* E   = (const float*)d_in[2];   // (NF, 4, 4)
    const int*   cam = (const int*)d_in[3];     // (NR,) int32

    int nf = in_sizes[0] / 3;
    if (nf > NF_MAX) nf = NF_MAX;
    int nr = in_sizes[3];

    precompute_kernel<<<(nf + 127) / 128, 128>>>(r, t, E, nf);

    int n_chunks = nr * 4;
    int threads = 256;
    int per_block = threads * GATHER_ILP;
    int grid = (n_chunks + per_block - 1) / per_block;
    gather_kernel<<<grid, threads>>>(cam, (float4*)d_out, n_chunks, nf);
}

// round 7
// speedup vs baseline: 1.0235x; 1.0235x over previous
#include <cuda_runtime.h>

// Per-frame precomputed matrices: M[f] = initial_extrinsics[f] @ inv(c2w[f])
// 10000 frames x 4 float4 rows = 640 KB static device scratch.
#define NF_MAX 10000
__device__ __align__(128) float4 g_M[NF_MAX * 4];

// ---------------------------------------------------------------------------
// Phase 1: per-frame precompute, all fp32. 64-thread blocks -> 157 blocks
// spread over all SMs (latency-bound tiny kernel).
// ---------------------------------------------------------------------------
__global__ void precompute_kernel(const float* __restrict__ r,
                                  const float* __restrict__ t,
                                  const float* __restrict__ E,
                                  int nf) {
    int f = blockIdx.x * blockDim.x + threadIdx.x;
    if (f >= nf) return;

    float v0 = r[3 * f + 0];
    float v1 = r[3 * f + 1];
    float v2 = r[3 * f + 2];

    float n = sqrtf(v0 * v0 + v1 * v1 + v2 * v2) + 1e-15f;
    float sn, cn;
    __sincosf(n, &sn, &cn);
    float a = sn / n;
    float b = (1.0f - cn) / (n * n);

    // Reference vec2skew (transpose of standard skew):
    float S[3][3] = {{0.0f,  v2, -v1},
                     {-v2, 0.0f,  v0},
                     { v1, -v0, 0.0f}};

    float S2[3][3];
#pragma unroll
    for (int i = 0; i < 3; i++)
#pragma unroll
        for (int j = 0; j < 3; j++)
            S2[i][j] = S[i][0] * S[0][j] + S[i][1] * S[1][j] + S[i][2] * S[2][j];

    float R[3][3];
#pragma unroll
    for (int i = 0; i < 3; i++)
#pragma unroll
        for (int j = 0; j < 3; j++)
            R[i][j] = (i == j ? 1.0f : 0.0f) + a * S[i][j] + b * S2[i][j];

    // rigid inverse of c2w
    float tv0 = t[3 * f + 0];
    float tv1 = t[3 * f + 1];
    float tv2 = t[3 * f + 2];

    float Inv[3][4];
#pragma unroll
    for (int i = 0; i < 3; i++) {
        Inv[i][0] = R[0][i];
        Inv[i][1] = R[1][i];
        Inv[i][2] = R[2][i];
        Inv[i][3] = -(R[0][i] * tv0 + R[1][i] * tv1 + R[2][i] * tv2);
    }

    const float4* E0 = (const float4*)(E + 16 * f);
#pragma unroll
    for (int i = 0; i < 4; i++) {
        float4 e = E0[i];
        float4 row;
        row.x = e.x * Inv[0][0] + e.y * Inv[1][0] + e.z * Inv[2][0];
        row.y = e.x * Inv[0][1] + e.y * Inv[1][1] + e.z * Inv[2][1];
        row.z = e.x * Inv[0][2] + e.y * Inv[1][2] + e.z * Inv[2][2];
        row.w = e.x * Inv[0][3] + e.y * Inv[1][3] + e.z * Inv[2][3] + e.w;
        g_M[f * 4 + i] = row;
    }
}

// ---------------------------------------------------------------------------
// Phase 2: gather. Quad-lane layout (4 lanes of a ray fetch its 64B entry in
// one warp LDG -> 1 demand wavefront/ray). Table reads via __ldcg (L2-only):
// the 640KB table thrashes 228KB L1; skipping fills removes ~2M fill
// wavefronts. ILP=4 keeps regs ~26 so occupancy stays >85% (R6 lesson:
// ILP=8 + ldcg ballooned regs to 48 and crashed occupancy).
// ---------------------------------------------------------------------------
#define GATHER_ILP 4
__global__ void __launch_bounds__(256) gather_kernel(
        const int* __restrict__ cam,
        float4* __restrict__ out,
        int n_chunks, int nf) {
    int base = blockIdx.x * (blockDim.x * GATHER_ILP) + threadIdx.x;

    if (base + (GATHER_ILP - 1) * blockDim.x < n_chunks) {
        float4 v[GATHER_ILP];
#pragma unroll
        for (int k = 0; k < GATHER_ILP; k++) {
            int c = base + k * blockDim.x;
            int ray = c >> 2;
            int q   = c & 3;
            int f = __ldg(&cam[ray]);
            f = min(max(f, 0), nf - 1);
            v[k] = __ldcg(&g_M[f * 4 + q]);   // L2-only, no L1 fill churn
        }
#pragma unroll
        for (int k = 0; k < GATHER_ILP; k++)
            out[base + k * blockDim.x] = v[k];
    } else {
#pragma unroll
        for (int k = 0; k < GATHER_ILP; k++) {
            int c = base + k * blockDim.x;
            if (c < n_chunks) {
                int ray = c >> 2;
                int q   = c & 3;
                int f = __ldg(&cam[ray]);
                f = min(max(f, 0), nf - 1);
                out[c] = __ldcg(&g_M[f * 4 + q]);
            }
        }
    }
}

extern "C" void kernel_launch(void* const* d_in, const int* in_sizes, int n_in,
                              void* d_out, int out_size) {
    const float* r   = (const float*)d_in[0];   // (NF, 3)
    const float* t   = (const float*)d_in[1];   // (NF, 3)
    const float* E   = (const float*)d_in[2];   // (NF, 4, 4)
    const int*   cam = (const int*)d_in[3];     // (NR,) int32

    int nf = in_sizes[0] / 3;
    if (nf > NF_MAX) nf = NF_MAX;
    int nr = in_sizes[3];

    precompute_kernel<<<(nf + 63) / 64, 64>>>(r, t, E, nf);

    int n_chunks = nr * 4;
    int threads = 256;
    int per_block = threads * GATHER_ILP;
    int grid = (n_chunks + per_block - 1) / per_block;
    gather_kernel<<<grid, threads>>>(cam, (float4*)d_out, n_chunks, nf);
}

// round 8
// speedup vs baseline: 1.0827x; 1.0579x over previous
#include <cuda_runtime.h>

// Per-frame precomputed matrices: M[f] = initial_extrinsics[f] @ inv(c2w[f])
// 10000 frames x 4 float4 rows = 640 KB static device scratch.
#define NF_MAX 10000
__device__ __align__(128) float4 g_M[NF_MAX * 4];

// ---------------------------------------------------------------------------
// Phase 1: per-frame precompute, all fp32, 64-thread blocks (157 blocks over
// 148 SMs; latency-bound tiny kernel wants spread, not fat blocks).
// ---------------------------------------------------------------------------
__global__ void precompute_kernel(const float* __restrict__ r,
                                  const float* __restrict__ t,
                                  const float* __restrict__ E,
                                  int nf) {
    int f = blockIdx.x * blockDim.x + threadIdx.x;
    if (f >= nf) return;

    float v0 = r[3 * f + 0];
    float v1 = r[3 * f + 1];
    float v2 = r[3 * f + 2];

    float n = sqrtf(v0 * v0 + v1 * v1 + v2 * v2) + 1e-15f;
    float sn, cn;
    __sincosf(n, &sn, &cn);
    float a = sn / n;
    float b = (1.0f - cn) / (n * n);

    // Reference vec2skew (transpose of standard skew):
    float S[3][3] = {{0.0f,  v2, -v1},
                     {-v2, 0.0f,  v0},
                     { v1, -v0, 0.0f}};

    float S2[3][3];
#pragma unroll
    for (int i = 0; i < 3; i++)
#pragma unroll
        for (int j = 0; j < 3; j++)
            S2[i][j] = S[i][0] * S[0][j] + S[i][1] * S[1][j] + S[i][2] * S[2][j];

    float R[3][3];
#pragma unroll
    for (int i = 0; i < 3; i++)
#pragma unroll
        for (int j = 0; j < 3; j++)
            R[i][j] = (i == j ? 1.0f : 0.0f) + a * S[i][j] + b * S2[i][j];

    // rigid inverse of c2w
    float tv0 = t[3 * f + 0];
    float tv1 = t[3 * f + 1];
    float tv2 = t[3 * f + 2];

    float Inv[3][4];
#pragma unroll
    for (int i = 0; i < 3; i++) {
        Inv[i][0] = R[0][i];
        Inv[i][1] = R[1][i];
        Inv[i][2] = R[2][i];
        Inv[i][3] = -(R[0][i] * tv0 + R[1][i] * tv1 + R[2][i] * tv2);
    }

    const float4* E0 = (const float4*)(E + 16 * f);
#pragma unroll
    for (int i = 0; i < 4; i++) {
        float4 e = E0[i];
        float4 row;
        row.x = e.x * Inv[0][0] + e.y * Inv[1][0] + e.z * Inv[2][0];
        row.y = e.x * Inv[0][1] + e.y * Inv[1][1] + e.z * Inv[2][1];
        row.z = e.x * Inv[0][2] + e.y * Inv[1][2] + e.z * Inv[2][2];
        row.w = e.x * Inv[0][3] + e.y * Inv[1][3] + e.z * Inv[2][3] + e.w;
        g_M[f * 4 + i] = row;
    }
}

// ---------------------------------------------------------------------------
// Phase 2: gather. Measured model: kernel runs at ~90% of the chip LTS cap
// (264 MB through L2 per iter). Quad-lane layout (1 demand wavefront per
// random 64B entry), __ldg so L1 retains ~30% of table reads (the only
// knob that cuts LTS traffic), ILP=4 (regs 28 -> occ >83%).
// ---------------------------------------------------------------------------
#define GATHER_ILP 4
__global__ void __launch_bounds__(256) gather_kernel(
        const int* __restrict__ cam,
        float4* __restrict__ out,
        int n_chunks, int nf) {
    int base = blockIdx.x * (blockDim.x * GATHER_ILP) + threadIdx.x;

    if (base + (GATHER_ILP - 1) * blockDim.x < n_chunks) {
        float4 v[GATHER_ILP];
#pragma unroll
        for (int k = 0; k < GATHER_ILP; k++) {
            int c = base + k * blockDim.x;
            int ray = c >> 2;
            int q   = c & 3;
            int f = __ldg(&cam[ray]);
            f = min(max(f, 0), nf - 1);
            v[k] = __ldg(&g_M[f * 4 + q]);
        }
#pragma unroll
        for (int k = 0; k < GATHER_ILP; k++)
            out[base + k * blockDim.x] = v[k];
    } else {
#pragma unroll
        for (int k = 0; k < GATHER_ILP; k++) {
            int c = base + k * blockDim.x;
            if (c < n_chunks) {
                int ray = c >> 2;
                int q   = c & 3;
                int f = __ldg(&cam[ray]);
                f = min(max(f, 0), nf - 1);
                out[c] = __ldg(&g_M[f * 4 + q]);
            }
        }
    }
}

extern "C" void kernel_launch(void* const* d_in, const int* in_sizes, int n_in,
                              void* d_out, int out_size) {
    const float* r   = (const float*)d_in[0];   // (NF, 3)
    const float* t   = (const float*)d_in[1];   // (NF, 3)
    const float* E   = (const float*)d_in[2];   // (NF, 4, 4)
    const int*   cam = (const int*)d_in[3];     // (NR,) int32

    int nf = in_sizes[0] / 3;
    if (nf > NF_MAX) nf = NF_MAX;
    int nr = in_sizes[3];

    precompute_kernel<<<(nf + 63) / 64, 64>>>(r, t, E, nf);

    int n_chunks = nr * 4;
    int threads = 256;
    int per_block = threads * GATHER_ILP;
    int grid = (n_chunks + per_block - 1) / per_block;
    gather_kernel<<<grid, threads>>>(cam, (float4*)d_out, n_chunks, nf);
}